// round 2
// baseline (speedup 1.0000x reference)
#include <cuda_runtime.h>

#define BATCH 20
#define SEQ   4096
#define EMB   256
#define NB    32            // SEQ / BLOCK
#define BLK   128
#define CTX   384           // 3 * BLK
#define MROWS (BATCH*SEQ)   // 81920

// Scratch (device globals; no allocations allowed)
__device__ float g_q[MROWS*EMB];
__device__ float g_k[MROWS*EMB];
__device__ float g_v[MROWS*EMB];
__device__ float g_p[(size_t)BATCH*NB*BLK*CTX];   // logits / probs
__device__ float g_att[MROWS*EMB];                // attention out (permuted rows)

struct Smem {
    float As[8][128];   // [k][m]
    float Bs[8][128];   // [k][n]
};

// ---- shared-tile loaders --------------------------------------------------

// A row-major [., lda]; tile rows 0..127 (A pre-offset to m0 row), cols k0..k0+7
__device__ __forceinline__ void load_A(Smem& sm, const float* __restrict__ A,
                                       int lda, int k0, int t) {
    int ar = t >> 1, ac4 = (t & 1) * 4;
    float4 v = *(const float4*)(A + (size_t)ar * lda + k0 + ac4);
    sm.As[ac4 + 0][ar] = v.x;
    sm.As[ac4 + 1][ar] = v.y;
    sm.As[ac4 + 2][ar] = v.z;
    sm.As[ac4 + 3][ar] = v.w;
}

// B row-major [K, ldb]; tile rows k0..k0+7, cols n0..n0+127
__device__ __forceinline__ void load_B(Smem& sm, const float* __restrict__ B,
                                       int ldb, int k0, int n0, int t) {
    int br = t >> 5, bc4 = (t & 31) * 4;
    *(float4*)&sm.Bs[br][bc4] = *(const float4*)(B + (size_t)(k0 + br) * ldb + n0 + bc4);
}

// B = Kc^T: Kc row-major [128 ctx rows, ldb]; want Bs[kd][ctxrow]
__device__ __forceinline__ void load_BT(Smem& sm, const float* __restrict__ Kc,
                                        int ldb, int k0, int t) {
    int nr = t >> 1, nc4 = (t & 1) * 4;
    float4 v = *(const float4*)(Kc + (size_t)nr * ldb + k0 + nc4);
    sm.Bs[nc4 + 0][nr] = v.x;
    sm.Bs[nc4 + 1][nr] = v.y;
    sm.Bs[nc4 + 2][nr] = v.z;
    sm.Bs[nc4 + 3][nr] = v.w;
}

// ---- 8x8 register-tile inner product over one 8-deep K slab ---------------
__device__ __forceinline__ void tile_compute(const Smem& sm, float acc[8][8],
                                             int tx, int ty) {
#pragma unroll
    for (int k = 0; k < 8; k++) {
        float a[8], b[8];
        *(float4*)(a)     = *(const float4*)&sm.As[k][ty * 8];
        *(float4*)(a + 4) = *(const float4*)&sm.As[k][ty * 8 + 4];
        *(float4*)(b)     = *(const float4*)&sm.Bs[k][tx * 8];
        *(float4*)(b + 4) = *(const float4*)&sm.Bs[k][tx * 8 + 4];
#pragma unroll
        for (int i = 0; i < 8; i++)
#pragma unroll
            for (int j = 0; j < 8; j++)
                acc[i][j] = fmaf(a[i], b[j], acc[i][j]);
    }
}

// ---- kernel 1: fused QKV projections --------------------------------------
__global__ __launch_bounds__(256, 2)
void qkv_kernel(const float* __restrict__ x, const float* __restrict__ Wq,
                const float* __restrict__ Wk, const float* __restrict__ Wv) {
    __shared__ Smem sm;
    int t = threadIdx.x;
    const float* W;
    float* C;
    if (blockIdx.z == 0)      { W = Wq; C = g_q; }
    else if (blockIdx.z == 1) { W = Wk; C = g_k; }
    else                      { W = Wv; C = g_v; }

    int m0 = blockIdx.x * 128, n0 = blockIdx.y * 128;
    const float* A = x + (size_t)m0 * EMB;

    float acc[8][8] = {};
    for (int k0 = 0; k0 < EMB; k0 += 8) {
        load_A(sm, A, EMB, k0, t);
        load_B(sm, W, EMB, k0, n0, t);
        __syncthreads();
        tile_compute(sm, acc, t & 15, t >> 4);
        __syncthreads();
    }
    int tx = t & 15, ty = t >> 4;
    float* Cp = C + (size_t)(m0 + ty * 8) * EMB + n0 + tx * 8;
#pragma unroll
    for (int i = 0; i < 8; i++) {
        *(float4*)(Cp + (size_t)i * EMB)     = *(float4*)&acc[i][0];
        *(float4*)(Cp + (size_t)i * EMB + 4) = *(float4*)&acc[i][4];
    }
}

// ---- kernel 2: logits = Q @ Kc^T / 16 (zero tiles at edges) ---------------
__global__ __launch_bounds__(256, 2)
void qk_kernel() {
    __shared__ Smem sm;
    int t = threadIdx.x;
    int cj = blockIdx.x;       // context block within window: 0..2
    int nbi = blockIdx.y;      // 0..31
    int b = blockIdx.z;        // 0..19
    int gb = nbi + cj - 1;

    float* P = g_p + ((size_t)(b * NB + nbi) * BLK) * CTX + cj * BLK;

    if (gb < 0 || gb >= NB) {
        // zero-padded context block -> logits exactly 0 (matches jnp.pad)
        for (int i = t; i < 128 * 32; i += 256) {
            int m = i >> 5, n4 = (i & 31) * 4;
            *(float4*)(P + (size_t)m * CTX + n4) = make_float4(0.f, 0.f, 0.f, 0.f);
        }
        return;
    }

    const float* A  = g_q + (size_t)(b * SEQ + nbi * BLK) * EMB;
    const float* Kp = g_k + (size_t)(b * SEQ + gb * BLK) * EMB;

    float acc[8][8] = {};
    for (int k0 = 0; k0 < EMB; k0 += 8) {
        load_A(sm, A, EMB, k0, t);
        load_BT(sm, Kp, EMB, k0, t);
        __syncthreads();
        tile_compute(sm, acc, t & 15, t >> 4);
        __syncthreads();
    }
    int tx = t & 15, ty = t >> 4;
    const float scale = 0.0625f;  // 1/sqrt(256)
#pragma unroll
    for (int i = 0; i < 8; i++) {
        float4 v0 = make_float4(acc[i][0] * scale, acc[i][1] * scale,
                                acc[i][2] * scale, acc[i][3] * scale);
        float4 v1 = make_float4(acc[i][4] * scale, acc[i][5] * scale,
                                acc[i][6] * scale, acc[i][7] * scale);
        float* row = P + (size_t)(ty * 8 + i) * CTX + tx * 8;
        *(float4*)(row)     = v0;
        *(float4*)(row + 4) = v1;
    }
}

// ---- kernel 3: softmax over the 384-wide context (warp per row) -----------
__global__ __launch_bounds__(256)
void softmax_kernel() {
    int row = blockIdx.x * 8 + (threadIdx.x >> 5);
    int lane = threadIdx.x & 31;
    float* p = g_p + (size_t)row * CTX;

    float v[12];
#pragma unroll
    for (int i = 0; i < 12; i++) v[i] = p[lane + i * 32];

    float m = v[0];
#pragma unroll
    for (int i = 1; i < 12; i++) m = fmaxf(m, v[i]);
#pragma unroll
    for (int off = 16; off > 0; off >>= 1)
        m = fmaxf(m, __shfl_xor_sync(0xFFFFFFFFu, m, off));

    float s = 0.f;
#pragma unroll
    for (int i = 0; i < 12; i++) { v[i] = __expf(v[i] - m); s += v[i]; }
#pragma unroll
    for (int off = 16; off > 0; off >>= 1)
        s += __shfl_xor_sync(0xFFFFFFFFu, s, off);

    float inv = 1.f / s;
#pragma unroll
    for (int i = 0; i < 12; i++) p[lane + i * 32] = v[i] * inv;
}

// ---- kernel 4: O = P @ Vc, stored with (nb,b) row permutation -------------
__global__ __launch_bounds__(256, 2)
void av_kernel() {
    __shared__ Smem sm;
    int t = threadIdx.x;
    int nt = blockIdx.x;   // 0..1 (EMB tile)
    int nbi = blockIdx.y;
    int b = blockIdx.z;

    const float* A = g_p + (size_t)((b * NB + nbi) * BLK) * CTX;
    int n0 = nt * 128;

    float acc[8][8] = {};
    for (int cb = 0; cb < 3; cb++) {
        int gb = nbi + cb - 1;
        if (gb < 0 || gb >= NB) continue;   // padded V block is zero
        const float* V = g_v + (size_t)(b * SEQ + gb * BLK) * EMB;
        for (int k0 = 0; k0 < BLK; k0 += 8) {
            load_A(sm, A + cb * BLK, CTX, k0, t);
            load_B(sm, V, EMB, k0, n0, t);
            __syncthreads();
            tile_compute(sm, acc, t & 15, t >> 4);
            __syncthreads();
        }
    }
    int tx = t & 15, ty = t >> 4;
    int rowbase = nbi * (BATCH * BLK) + b * BLK;   // reference transpose (1,0,2,3)
    float* Cp = g_att + (size_t)(rowbase + ty * 8) * EMB + n0 + tx * 8;
#pragma unroll
    for (int i = 0; i < 8; i++) {
        *(float4*)(Cp + (size_t)i * EMB)     = *(float4*)&acc[i][0];
        *(float4*)(Cp + (size_t)i * EMB + 4) = *(float4*)&acc[i][4];
    }
}

// ---- kernel 5: final projection + bias ------------------------------------
__global__ __launch_bounds__(256, 2)
void out_kernel(const float* __restrict__ Wo, const float* __restrict__ bo,
                float* __restrict__ out) {
    __shared__ Smem sm;
    int t = threadIdx.x;
    int m0 = blockIdx.x * 128, n0 = blockIdx.y * 128;
    const float* A = g_att + (size_t)m0 * EMB;

    float acc[8][8] = {};
    for (int k0 = 0; k0 < EMB; k0 += 8) {
        load_A(sm, A, EMB, k0, t);
        load_B(sm, Wo, EMB, k0, n0, t);
        __syncthreads();
        tile_compute(sm, acc, t & 15, t >> 4);
        __syncthreads();
    }
    int tx = t & 15, ty = t >> 4;
    float bias[8];
#pragma unroll
    for (int j = 0; j < 8; j++) bias[j] = bo[n0 + tx * 8 + j];

    float* Cp = out + (size_t)(m0 + ty * 8) * EMB + n0 + tx * 8;
#pragma unroll
    for (int i = 0; i < 8; i++) {
        float4 v0 = make_float4(acc[i][0] + bias[0], acc[i][1] + bias[1],
                                acc[i][2] + bias[2], acc[i][3] + bias[3]);
        float4 v1 = make_float4(acc[i][4] + bias[4], acc[i][5] + bias[5],
                                acc[i][6] + bias[6], acc[i][7] + bias[7]);
        *(float4*)(Cp + (size_t)i * EMB)     = v0;
        *(float4*)(Cp + (size_t)i * EMB + 4) = v1;
    }
}

// ---- launch ---------------------------------------------------------------
extern "C" void kernel_launch(void* const* d_in, const int* in_sizes, int n_in,
                              void* d_out, int out_size) {
    const float* x  = (const float*)d_in[0];
    const float* Wq = (const float*)d_in[1];
    const float* Wk = (const float*)d_in[2];
    const float* Wv = (const float*)d_in[3];
    const float* Wo = (const float*)d_in[4];
    const float* bo = (const float*)d_in[5];
    float* out = (float*)d_out;

    qkv_kernel<<<dim3(MROWS / 128, EMB / 128, 3), 256>>>(x, Wq, Wk, Wv);
    qk_kernel<<<dim3(3, NB, BATCH), 256>>>();
    softmax_kernel<<<(MROWS / 8), 256>>>();
    av_kernel<<<dim3(2, NB, BATCH), 256>>>();
    out_kernel<<<dim3(MROWS / 128, EMB / 128), 256>>>(Wo, bo, out);
}

// round 4
// speedup vs baseline: 2.6495x; 2.6495x over previous
#include <cuda_runtime.h>
#include <cstdint>

#define BATCH 20
#define SEQ   4096
#define EMB   256
#define NB    32
#define BLK   128
#define CTX   384
#define MROWS (BATCH*SEQ)

#define SA 36      // A smem stride (floats): bank = 4*g + tig, conflict-free
#define SB 136     // B smem stride (floats): bank = 8*tig + n, conflict-free
#define SMEMB ((2*128*SA + 2*32*SB) * 4)   // 71680 bytes

// Scratch (device globals; no allocations allowed)
__device__ float g_xc[MROWS*EMB];                 // x rounded to tf32
__device__ float g_wc[4*EMB*EMB];                 // Wq,Wk,Wv,Wo rounded to tf32
__device__ float g_q [MROWS*EMB];
__device__ float g_kT[MROWS*EMB];                 // K transposed per block: [blk][emb][token]
__device__ float g_v [MROWS*EMB];
__device__ float g_p [(size_t)BATCH*NB*BLK*CTX];
__device__ float g_att[MROWS*EMB];

// ---- primitives -----------------------------------------------------------

__device__ __forceinline__ uint32_t smem_u32(const void* p) {
    uint32_t a;
    asm("{ .reg .u64 t; cvta.to.shared.u64 t, %1; cvt.u32.u64 %0, t; }"
        : "=r"(a) : "l"(p));
    return a;
}

__device__ __forceinline__ float totf(float x) {
    uint32_t r;
    asm("cvt.rna.tf32.f32 %0, %1;" : "=r"(r) : "f"(x));
    return __uint_as_float(r);
}

__device__ __forceinline__ void cpa16(uint32_t dst, const float* src) {
    asm volatile("cp.async.cg.shared.global [%0], [%1], 16;" :: "r"(dst), "l"(src));
}
#define CP_COMMIT() asm volatile("cp.async.commit_group;" ::: "memory")
#define CP_WAIT1()  asm volatile("cp.async.wait_group 1;" ::: "memory")
#define CP_WAIT0()  asm volatile("cp.async.wait_group 0;" ::: "memory")

__device__ __forceinline__ void mma8(float c[4], float a0, float a1, float a2, float a3,
                                     float b0, float b1) {
    asm volatile(
        "mma.sync.aligned.m16n8k8.row.col.f32.tf32.tf32.f32 "
        "{%0,%1,%2,%3}, {%4,%5,%6,%7}, {%8,%9}, {%0,%1,%2,%3};"
        : "+f"(c[0]), "+f"(c[1]), "+f"(c[2]), "+f"(c[3])
        : "r"(__float_as_uint(a0)), "r"(__float_as_uint(a1)),
          "r"(__float_as_uint(a2)), "r"(__float_as_uint(a3)),
          "r"(__float_as_uint(b0)), "r"(__float_as_uint(b1)));
}

// ---- chunk copies (A: 128 rows x 32 k; B: 32 k x 128 n) -------------------

__device__ __forceinline__ void cpA(uint32_t sA, const float* __restrict__ src,
                                    int ld, int t) {
#pragma unroll
    for (int j = 0; j < 4; j++) {
        int idx = j * 256 + t;
        int m = idx >> 3, k4 = (idx & 7) << 2;
        cpa16(sA + (uint32_t)(m * SA + k4) * 4, src + (size_t)m * ld + k4);
    }
}

__device__ __forceinline__ void cpB(uint32_t sB, const float* __restrict__ src,
                                    int ld, int t) {
#pragma unroll
    for (int j = 0; j < 4; j++) {
        int idx = j * 256 + t;
        int k = idx >> 5, n4 = (idx & 31) << 2;
        cpa16(sB + (uint32_t)(k * SB + n4) * 4, src + (size_t)k * ld + n4);
    }
}

// ---- warp-tile compute for one 32-deep K chunk ----------------------------

__device__ __forceinline__ void mma_chunk(const float* __restrict__ As,
                                          const float* __restrict__ Bs,
                                          float acc[16][4], int t) {
    int lane = t & 31, w = t >> 5;
    int g = lane >> 2, tig = lane & 3;
    int mbase = (w >> 2) * 64 + g;
    int nbase = (w & 3) * 32 + g;
#pragma unroll
    for (int s = 0; s < 4; s++) {
        int k = s * 8 + tig;
        float b[4][2];
#pragma unroll
        for (int nt = 0; nt < 4; nt++) {
            b[nt][0] = Bs[k * SB + nbase + nt * 8];
            b[nt][1] = Bs[(k + 4) * SB + nbase + nt * 8];
        }
#pragma unroll
        for (int mt = 0; mt < 4; mt++) {
            int m = mbase + mt * 16;
            float a0 = As[m * SA + k];
            float a1 = As[(m + 8) * SA + k];
            float a2 = As[m * SA + k + 4];
            float a3 = As[(m + 8) * SA + k + 4];
#pragma unroll
            for (int nt = 0; nt < 4; nt++)
                mma8(acc[mt * 4 + nt], a0, a1, a2, a3, b[nt][0], b[nt][1]);
        }
    }
}

// ---- double-buffered pipeline over nC chunks ------------------------------

__device__ __forceinline__ void gemm_pipeline(const float* const* aS, const float* const* bS,
                                              int nC, int lda, int ldb,
                                              float acc[16][4], char* smem, int t) {
    float* A0 = (float*)smem;
    float* A1 = A0 + 128 * SA;
    float* B0 = A1 + 128 * SA;
    float* B1 = B0 + 32 * SB;
    float* Ab[2] = {A0, A1};
    float* Bb[2] = {B0, B1};
    uint32_t aAddr[2] = {smem_u32(A0), smem_u32(A1)};
    uint32_t bAddr[2] = {smem_u32(B0), smem_u32(B1)};

    cpA(aAddr[0], aS[0], lda, t);
    cpB(bAddr[0], bS[0], ldb, t);
    CP_COMMIT();

    for (int c = 0; c < nC; c++) {
        if (c + 1 < nC) {
            cpA(aAddr[(c + 1) & 1], aS[c + 1], lda, t);
            cpB(bAddr[(c + 1) & 1], bS[c + 1], ldb, t);
            CP_COMMIT();
            CP_WAIT1();
        } else {
            CP_WAIT0();
        }
        __syncthreads();
        mma_chunk(Ab[c & 1], Bb[c & 1], acc, t);
        __syncthreads();
    }
}

// ---- standard epilogue ----------------------------------------------------

__device__ __forceinline__ void store_std(float acc[16][4], float* __restrict__ C, int ldc,
                                          float scale, const float* __restrict__ bias,
                                          bool rnd, int t) {
    int lane = t & 31, w = t >> 5;
    int g = lane >> 2, tig = lane & 3;
    int mbase = (w >> 2) * 64 + g;
    int nbase = (w & 3) * 32 + 2 * tig;
#pragma unroll
    for (int mt = 0; mt < 4; mt++) {
#pragma unroll
        for (int nt = 0; nt < 4; nt++) {
            float* c4 = acc[mt * 4 + nt];
            int m = mbase + mt * 16, n = nbase + nt * 8;
            float v0 = c4[0] * scale, v1 = c4[1] * scale;
            float v2 = c4[2] * scale, v3 = c4[3] * scale;
            if (bias) { v0 += bias[n]; v1 += bias[n + 1]; v2 += bias[n]; v3 += bias[n + 1]; }
            if (rnd) { v0 = totf(v0); v1 = totf(v1); v2 = totf(v2); v3 = totf(v3); }
            *(float2*)(C + (size_t)m * ldc + n)       = make_float2(v0, v1);
            *(float2*)(C + (size_t)(m + 8) * ldc + n) = make_float2(v2, v3);
        }
    }
}

// ---- kernel: pre-convert to tf32 ------------------------------------------

__global__ __launch_bounds__(256)
void cvt_kernel(const float* __restrict__ src, float* __restrict__ dst, int n4) {
    int i = blockIdx.x * 256 + threadIdx.x;
    if (i < n4) {
        float4 v = ((const float4*)src)[i];
        v.x = totf(v.x); v.y = totf(v.y); v.z = totf(v.z); v.w = totf(v.w);
        ((float4*)dst)[i] = v;
    }
}

// ---- kernel 1: QKV projections --------------------------------------------

__global__ __launch_bounds__(256)
void qkv_mma() {
    extern __shared__ char smbuf[];
    int t = threadIdx.x;
    int z = blockIdx.z;
    int m0 = blockIdx.x * 128, n0 = blockIdx.y * 128;
    const float* W = g_wc + (size_t)z * EMB * EMB;

    const float* aS[8];
    const float* bS[8];
#pragma unroll
    for (int c = 0; c < 8; c++) {
        aS[c] = g_xc + (size_t)m0 * EMB + c * 32;
        bS[c] = W + (size_t)(c * 32) * EMB + n0;
    }
    float acc[16][4] = {};
    gemm_pipeline(aS, bS, 8, EMB, EMB, acc, smbuf, t);

    if (z == 1) {
        // transposed store: g_kT[m0*256 + (n0+n)*128 + m] = tf32(C[m][n])
        float* KT = g_kT + (size_t)m0 * EMB + (size_t)n0 * 128;
        int lane = t & 31, w = t >> 5;
        int g = lane >> 2, tig = lane & 3;
        int mbase = (w >> 2) * 64 + g;
        int nbase = (w & 3) * 32 + 2 * tig;
#pragma unroll
        for (int mt = 0; mt < 4; mt++) {
#pragma unroll
            for (int nt = 0; nt < 4; nt++) {
                float* c4 = acc[mt * 4 + nt];
                int m = mbase + mt * 16, n = nbase + nt * 8;
                KT[(size_t)n * 128 + m]           = totf(c4[0]);
                KT[(size_t)(n + 1) * 128 + m]     = totf(c4[1]);
                KT[(size_t)n * 128 + m + 8]       = totf(c4[2]);
                KT[(size_t)(n + 1) * 128 + m + 8] = totf(c4[3]);
            }
        }
    } else {
        float* C = (z == 0 ? g_q : g_v) + (size_t)m0 * EMB + n0;
        store_std(acc, C, EMB, 1.0f, nullptr, true, t);
    }
}

// ---- kernel 2: logits = Q @ K^T / 16 --------------------------------------

__global__ __launch_bounds__(256)
void qk_mma() {
    extern __shared__ char smbuf[];
    int t = threadIdx.x;
    int cj = blockIdx.x, nbi = blockIdx.y, b = blockIdx.z;
    int gb = nbi + cj - 1;
    float* P = g_p + ((size_t)(b * NB + nbi) * BLK) * CTX + cj * BLK;

    if (gb < 0 || gb >= NB) {
        for (int i = t; i < 128 * 32; i += 256) {
            int m = i >> 5, n4 = (i & 31) * 4;
            *(float4*)(P + (size_t)m * CTX + n4) = make_float4(0.f, 0.f, 0.f, 0.f);
        }
        return;
    }

    const float* Q  = g_q + (size_t)(b * SEQ + nbi * BLK) * EMB;
    const float* KT = g_kT + (size_t)(b * SEQ + gb * BLK) * EMB;   // [256 e][128 tok]

    const float* aS[8];
    const float* bS[8];
#pragma unroll
    for (int c = 0; c < 8; c++) {
        aS[c] = Q + c * 32;
        bS[c] = KT + (size_t)(c * 32) * 128;
    }
    float acc[16][4] = {};
    gemm_pipeline(aS, bS, 8, EMB, 128, acc, smbuf, t);
    store_std(acc, P, CTX, 0.0625f, nullptr, false, t);
}

// ---- kernel 3: softmax over 384-wide context (tf32-rounded store) ---------

__global__ __launch_bounds__(256)
void softmax_kernel() {
    int row = blockIdx.x * 8 + (threadIdx.x >> 5);
    int lane = threadIdx.x & 31;
    float* p = g_p + (size_t)row * CTX;

    float v[12];
#pragma unroll
    for (int i = 0; i < 12; i++) v[i] = p[lane + i * 32];
    float m = v[0];
#pragma unroll
    for (int i = 1; i < 12; i++) m = fmaxf(m, v[i]);
#pragma unroll
    for (int off = 16; off > 0; off >>= 1)
        m = fmaxf(m, __shfl_xor_sync(0xFFFFFFFFu, m, off));
    float s = 0.f;
#pragma unroll
    for (int i = 0; i < 12; i++) { v[i] = __expf(v[i] - m); s += v[i]; }
#pragma unroll
    for (int off = 16; off > 0; off >>= 1)
        s += __shfl_xor_sync(0xFFFFFFFFu, s, off);
    float inv = 1.f / s;
#pragma unroll
    for (int i = 0; i < 12; i++) p[lane + i * 32] = totf(v[i] * inv);
}

// ---- kernel 4: O = P @ Vc, permuted store ---------------------------------

__global__ __launch_bounds__(256)
void av_mma() {
    extern __shared__ char smbuf[];
    int t = threadIdx.x;
    int nt = blockIdx.x, nbi = blockIdx.y, b = blockIdx.z;
    int n0 = nt * 128;
    const float* Pb = g_p + (size_t)((b * NB + nbi) * BLK) * CTX;

    const float* aS[12];
    const float* bS[12];
    int nC = 0;
    for (int cb = 0; cb < 3; cb++) {
        int gb = nbi + cb - 1;
        if (gb < 0 || gb >= NB) continue;
        for (int kc = 0; kc < 4; kc++) {
            aS[nC] = Pb + cb * 128 + kc * 32;
            bS[nC] = g_v + (size_t)(b * SEQ + gb * BLK + kc * 32) * EMB + n0;
            nC++;
        }
    }
    float acc[16][4] = {};
    gemm_pipeline(aS, bS, nC, CTX, EMB, acc, smbuf, t);

    int rowbase = nbi * (BATCH * BLK) + b * BLK;   // reference transpose (1,0,2,3)
    store_std(acc, g_att + (size_t)rowbase * EMB + n0, EMB, 1.0f, nullptr, true, t);
}

// ---- kernel 5: out = att @ Wo + bo ----------------------------------------

__global__ __launch_bounds__(256)
void out_mma(const float* __restrict__ bo, float* __restrict__ out) {
    extern __shared__ char smbuf[];
    int t = threadIdx.x;
    int m0 = blockIdx.x * 128, n0 = blockIdx.y * 128;
    const float* W = g_wc + (size_t)3 * EMB * EMB;

    const float* aS[8];
    const float* bS[8];
#pragma unroll
    for (int c = 0; c < 8; c++) {
        aS[c] = g_att + (size_t)m0 * EMB + c * 32;
        bS[c] = W + (size_t)(c * 32) * EMB + n0;
    }
    float acc[16][4] = {};
    gemm_pipeline(aS, bS, 8, EMB, EMB, acc, smbuf, t);
    store_std(acc, out + (size_t)m0 * EMB + n0, EMB, 1.0f, bo + n0, false, t);
}

// ---- launch ---------------------------------------------------------------

extern "C" void kernel_launch(void* const* d_in, const int* in_sizes, int n_in,
                              void* d_out, int out_size) {
    const float* x  = (const float*)d_in[0];
    const float* Wq = (const float*)d_in[1];
    const float* Wk = (const float*)d_in[2];
    const float* Wv = (const float*)d_in[3];
    const float* Wo = (const float*)d_in[4];
    const float* bo = (const float*)d_in[5];
    float* out = (float*)d_out;

    cudaFuncSetAttribute(qkv_mma, cudaFuncAttributeMaxDynamicSharedMemorySize, SMEMB);
    cudaFuncSetAttribute(qk_mma,  cudaFuncAttributeMaxDynamicSharedMemorySize, SMEMB);
    cudaFuncSetAttribute(av_mma,  cudaFuncAttributeMaxDynamicSharedMemorySize, SMEMB);
    cudaFuncSetAttribute(out_mma, cudaFuncAttributeMaxDynamicSharedMemorySize, SMEMB);

    float* xc = nullptr; float* wc = nullptr;
    cudaGetSymbolAddress((void**)&xc, g_xc);
    cudaGetSymbolAddress((void**)&wc, g_wc);

    cvt_kernel<<<(MROWS * EMB / 4 + 255) / 256, 256>>>(x, xc, MROWS * EMB / 4);
    cvt_kernel<<<(EMB * EMB / 4 + 255) / 256, 256>>>(Wq, wc + 0 * EMB * EMB, EMB * EMB / 4);
    cvt_kernel<<<(EMB * EMB / 4 + 255) / 256, 256>>>(Wk, wc + 1 * EMB * EMB, EMB * EMB / 4);
    cvt_kernel<<<(EMB * EMB / 4 + 255) / 256, 256>>>(Wv, wc + 2 * EMB * EMB, EMB * EMB / 4);
    cvt_kernel<<<(EMB * EMB / 4 + 255) / 256, 256>>>(Wo, wc + 3 * EMB * EMB, EMB * EMB / 4);

    qkv_mma<<<dim3(MROWS / 128, EMB / 128, 3), 256, SMEMB>>>();
    qk_mma<<<dim3(3, NB, BATCH), 256, SMEMB>>>();
    softmax_kernel<<<(MROWS / 8), 256>>>();
    av_mma<<<dim3(2, NB, BATCH), 256, SMEMB>>>();
    out_mma<<<dim3(MROWS / 128, EMB / 128), 256, SMEMB>>>(bo, out);
}